// round 16
// baseline (speedup 1.0000x reference)
#include <cuda_runtime.h>
#include <cuda_bf16.h>
#include <cuda_fp16.h>
#include <cstdint>

#define NNODES 50000
#define EDGES  800000
#define DIM    128
#define HEADS  8
#define SCAN_B 256
#define NBLK   ((NNODES + SCAN_B - 1) / SCAN_B)   // 196

// ---------------- scratch (static device arrays; no allocs allowed) ----------------
__device__ int    g_is64;
__device__ int2   g_ds[EDGES];           // (dst, src) int32
__device__ int    g_deg[NNODES];
__device__ int    g_rowoff[NNODES + 1];
__device__ int    g_cursor[NNODES];
__device__ int2   g_edge2[EDGES];        // (orig edge id, src node) in CSR order
__device__ int    g_blocksum[NBLK];
__device__ float  g_Q[(size_t)NNODES * DIM];
__device__ __half g_Kh[(size_t)NNODES * DIM];
__device__ __half g_Vh[(size_t)NNODES * DIM];
__device__ float  g_agg[(size_t)NNODES * DIM];
__device__ __nv_bfloat16 g_Wth[4 * DIM * DIM];  // transposed [N][K] hi
__device__ __nv_bfloat16 g_Wtl[4 * DIM * DIM];  // transposed [N][K] lo

// ---------------- helpers ----------------
__device__ __forceinline__ uint32_t smem_u32(const void* p) {
    uint32_t a;
    asm("{ .reg .u64 t; cvta.to.shared.u64 t, %1; cvt.u32.u64 %0, t; }" : "=r"(a) : "l"(p));
    return a;
}
__device__ __forceinline__ void ldsm_x4(uint32_t* r, uint32_t addr) {
    asm volatile("ldmatrix.sync.aligned.m8n8.x4.shared.b16 {%0,%1,%2,%3}, [%4];"
                 : "=r"(r[0]), "=r"(r[1]), "=r"(r[2]), "=r"(r[3]) : "r"(addr));
}
__device__ __forceinline__ void mma16816(float* d, const uint32_t* a, const uint32_t* b) {
    asm volatile(
        "mma.sync.aligned.m16n8k16.row.col.f32.bf16.bf16.f32 "
        "{%0,%1,%2,%3}, {%4,%5,%6,%7}, {%8,%9}, {%0,%1,%2,%3};"
        : "+f"(d[0]), "+f"(d[1]), "+f"(d[2]), "+f"(d[3])
        : "r"(a[0]), "r"(a[1]), "r"(a[2]), "r"(a[3]), "r"(b[0]), "r"(b[1]));
}

// ---------------- CSR build ----------------
__global__ void zero_detect_kernel(const void* ei) {
    int i = blockIdx.x * blockDim.x + threadIdx.x;
    if (i < NNODES) g_deg[i] = 0;
    if (i == 0) {
        const int* w = (const int*)ei;
        int is64 = 1;
        for (int t = 0; t < 64; t++) {
            int lo = w[2 * t], hi = w[2 * t + 1];
            if (hi != 0 || lo < 0 || lo >= NNODES) { is64 = 0; break; }
        }
        g_is64 = is64;
    }
}

__global__ void convert_hist_kernel(const void* ei) {
    int i = blockIdx.x * blockDim.x + threadIdx.x;
    if (i >= EDGES) return;
    int d, s;
    if (g_is64) {
        const long long* p = (const long long*)ei;
        d = (int)p[i];
        s = (int)p[EDGES + i];
    } else {
        const int* p = (const int*)ei;
        d = p[i];
        s = p[EDGES + i];
    }
    g_ds[i] = make_int2(d, s);
    atomicAdd(&g_deg[d], 1);
}

__global__ void blocksum_kernel() {
    __shared__ int red[SCAN_B];
    int i = blockIdx.x * SCAN_B + threadIdx.x;
    int v = (i < NNODES) ? g_deg[i] : 0;
    red[threadIdx.x] = v;
    __syncthreads();
    #pragma unroll
    for (int off = SCAN_B / 2; off > 0; off >>= 1) {
        if (threadIdx.x < off) red[threadIdx.x] += red[threadIdx.x + off];
        __syncthreads();
    }
    if (threadIdx.x == 0) g_blocksum[blockIdx.x] = red[0];
}

// fused: every block redundantly scans the 196 block sums, then scans its own
// 256 degrees and writes rowoff/cursor.
__global__ void writeoff_kernel() {
    __shared__ int sc[SCAN_B];
    const int tid = threadIdx.x;

    int bv = (tid < NBLK) ? g_blocksum[tid] : 0;
    sc[tid] = bv;
    __syncthreads();
    #pragma unroll
    for (int off = 1; off < SCAN_B; off <<= 1) {
        int u = (tid >= off) ? sc[tid - off] : 0;
        __syncthreads();
        sc[tid] += u;
        __syncthreads();
    }
    int blockoff = sc[blockIdx.x] - g_blocksum[blockIdx.x];
    int total = sc[NBLK - 1];
    __syncthreads();

    int i = blockIdx.x * SCAN_B + tid;
    int v = (i < NNODES) ? g_deg[i] : 0;
    sc[tid] = v;
    __syncthreads();
    #pragma unroll
    for (int off = 1; off < SCAN_B; off <<= 1) {
        int u = (tid >= off) ? sc[tid - off] : 0;
        __syncthreads();
        sc[tid] += u;
        __syncthreads();
    }
    if (i < NNODES) {
        int off = blockoff + sc[tid] - v;
        g_rowoff[i] = off;
        g_cursor[i] = off;
    }
    if (blockIdx.x == 0 && tid == 0) g_rowoff[NNODES] = total;
}

__global__ void scatter_kernel() {
    int i = blockIdx.x * blockDim.x + threadIdx.x;
    if (i >= EDGES) return;
    int2 ds = g_ds[i];
    int p = atomicAdd(&g_cursor[ds.x], 1);
    g_edge2[p] = make_int2(i, ds.y);
}

// ---------------- weight transpose + split ----------------
__global__ void conv_w_kernel(const float* __restrict__ W0, const float* __restrict__ W1,
                              const float* __restrict__ W2, const float* __restrict__ W3) {
    int i = blockIdx.x * blockDim.x + threadIdx.x;
    if (i >= 4 * DIM * DIM) return;
    int mat = i >> 14;
    int idx = i & 16383;
    int n = idx >> 7;
    int k = idx & 127;
    const float* W = (mat == 0) ? W0 : (mat == 1) ? W1 : (mat == 2) ? W2 : W3;
    float v = W[k * DIM + n];
    __nv_bfloat16 h = __float2bfloat16_rn(v);
    __nv_bfloat16 l = __float2bfloat16_rn(v - __bfloat162float(h));
    g_Wth[mat * DIM * DIM + idx] = h;
    g_Wtl[mat * DIM * DIM + idx] = l;
}

// ---------------- mma.sync split-bf16 GEMM, M-tile 64 (2 CTAs/SM) ----------------
// HALF_MASK bit w (compile-time constant at each call site): store output w as fp16.
#define LDA 136
#define A_TILE (64 * LDA * 2)             // 17408
#define B_TILE (128 * LDA * 2)            // 34816
#define OFF_AH 0
#define OFF_AL A_TILE
#define OFF_BH (2 * A_TILE)
#define OFF_BL (2 * A_TILE + B_TILE)
#define GSMEM  (2 * A_TILE + 2 * B_TILE)  // 104448 -> 2 CTAs/SM

__device__ __forceinline__ void gemm_mma_body(
    int HALF_MASK,
    const float* __restrict__ A,
    const __nv_bfloat16* __restrict__ Bh_all, const __nv_bfloat16* __restrict__ Bl_all,
    const float* __restrict__ bias0, const float* __restrict__ bias1,
    const float* __restrict__ bias2,
    void* __restrict__ C0, void* __restrict__ C1, void* __restrict__ C2,
    int count, int M) {
    extern __shared__ char sm[];
    const uint32_t sb = smem_u32(sm);
    const int tid = threadIdx.x, wid = tid >> 5, lane = tid & 31;
    const int bm = blockIdx.x * 64;

    // stage A (64 rows): load fp32, split to (hi, lo) bf16 in registers
    #pragma unroll
    for (int it = 0; it < 8; ++it) {
        int g = tid + it * 256;            // 0..2047, 4-col groups
        int row = g >> 5;
        int col = (g & 31) << 2;
        int gr = bm + row;
        float4 v = make_float4(0.f, 0.f, 0.f, 0.f);
        if (gr < M) v = *(const float4*)(A + (size_t)gr * DIM + col);
        float a[4] = {v.x, v.y, v.z, v.w};
        __nv_bfloat16 h[4], l[4];
        #pragma unroll
        for (int u = 0; u < 4; u++) {
            h[u] = __float2bfloat16_rn(a[u]);
            l[u] = __float2bfloat16_rn(a[u] - __bfloat162float(h[u]));
        }
        *(unsigned long long*)(sm + OFF_AH + (row * LDA + col) * 2) = *(unsigned long long*)h;
        *(unsigned long long*)(sm + OFF_AL + (row * LDA + col) * 2) = *(unsigned long long*)l;
    }

    // warp tiling: 2 warps in M (32 rows each), 4 warps in N (32 cols each)
    const int wm = wid & 1, wn = wid >> 1;
    const int m0 = wm * 32, n0 = wn * 32;
    const int g = lane >> 2, t = lane & 3;

    const int ar = lane & 15, ac = (lane >> 4) << 3;
    const int nn = (lane & 7) + ((lane >> 4) << 3);
    const int kkb = ((lane >> 3) & 1) << 3;

    #pragma unroll 1
    for (int w = 0; w < count; w++) {
        const __nv_bfloat16* Bh = Bh_all + (size_t)w * DIM * DIM;
        const __nv_bfloat16* Bl = Bl_all + (size_t)w * DIM * DIM;
        const float* bias = (w == 0) ? bias0 : (w == 1) ? bias1 : bias2;
        void* C = (w == 0) ? C0 : (w == 1) ? C1 : C2;
        const bool ashalf = (HALF_MASK >> w) & 1;

        __syncthreads();
        #pragma unroll
        for (int it = 0; it < 16; ++it) {
            int gg = tid + it * 256;       // 0..4095 (128 rows x 32 groups)
            int row = gg >> 5;
            int col = (gg & 31) << 2;
            *(unsigned long long*)(sm + OFF_BH + (row * LDA + col) * 2) =
                *(const unsigned long long*)(Bh + row * DIM + col);
            *(unsigned long long*)(sm + OFF_BL + (row * LDA + col) * 2) =
                *(const unsigned long long*)(Bl + row * DIM + col);
        }
        __syncthreads();

        float acc[2][4][4];
        #pragma unroll
        for (int mt = 0; mt < 2; mt++)
            #pragma unroll
            for (int nt = 0; nt < 4; nt++)
                #pragma unroll
                for (int u = 0; u < 4; u++) acc[mt][nt][u] = 0.f;

        #pragma unroll
        for (int k = 0; k < 8; k++) {
            const int k0 = k * 16;
            uint32_t aH[2][4], aL[2][4], bH[2][4], bL[2][4];
            #pragma unroll
            for (int mt = 0; mt < 2; mt++) {
                uint32_t off = ((m0 + mt * 16 + ar) * LDA + k0 + ac) * 2;
                ldsm_x4(aH[mt], sb + OFF_AH + off);
                ldsm_x4(aL[mt], sb + OFF_AL + off);
            }
            #pragma unroll
            for (int nb = 0; nb < 2; nb++) {
                uint32_t off = ((n0 + nb * 16 + nn) * LDA + k0 + kkb) * 2;
                ldsm_x4(bH[nb], sb + OFF_BH + off);
                ldsm_x4(bL[nb], sb + OFF_BL + off);
            }
            #pragma unroll
            for (int mt = 0; mt < 2; mt++)
                #pragma unroll
                for (int nb = 0; nb < 2; nb++) {
                    mma16816(acc[mt][2 * nb],     aH[mt], bH[nb]);
                    mma16816(acc[mt][2 * nb],     aH[mt], bL[nb]);
                    mma16816(acc[mt][2 * nb],     aL[mt], bH[nb]);
                    mma16816(acc[mt][2 * nb + 1], aH[mt], bH[nb] + 2);
                    mma16816(acc[mt][2 * nb + 1], aH[mt], bL[nb] + 2);
                    mma16816(acc[mt][2 * nb + 1], aL[mt], bH[nb] + 2);
                }
        }

        #pragma unroll
        for (int mt = 0; mt < 2; mt++) {
            int r0 = bm + m0 + mt * 16 + g;
            #pragma unroll
            for (int nt = 0; nt < 4; nt++) {
                int col = n0 + nt * 8 + 2 * t;
                float bx = __ldg(bias + col), by = __ldg(bias + col + 1);
                float o0 = acc[mt][nt][0] + bx, o1 = acc[mt][nt][1] + by;
                float o2 = acc[mt][nt][2] + bx, o3 = acc[mt][nt][3] + by;
                if (ashalf) {
                    __half* Ch = (__half*)C;
                    if (r0 < M)
                        *(__half2*)(Ch + (size_t)r0 * DIM + col) = __floats2half2_rn(o0, o1);
                    if (r0 + 8 < M)
                        *(__half2*)(Ch + (size_t)(r0 + 8) * DIM + col) = __floats2half2_rn(o2, o3);
                } else {
                    float* Cf = (float*)C;
                    if (r0 < M)
                        *(float2*)(Cf + (size_t)r0 * DIM + col) = make_float2(o0, o1);
                    if (r0 + 8 < M)
                        *(float2*)(Cf + (size_t)(r0 + 8) * DIM + col) = make_float2(o2, o3);
                }
            }
        }
    }
}

// two concrete instantiations (no templates — keep symbols plain)
__global__ __launch_bounds__(256) void gemm_mma_qkv(
    const float* __restrict__ A,
    const __nv_bfloat16* __restrict__ Bh_all, const __nv_bfloat16* __restrict__ Bl_all,
    const float* __restrict__ bias0, const float* __restrict__ bias1,
    const float* __restrict__ bias2,
    float* __restrict__ Cq, __half* __restrict__ Ck, __half* __restrict__ Cv, int M) {
    gemm_mma_body(0b110, A, Bh_all, Bl_all, bias0, bias1, bias2,
                  (void*)Cq, (void*)Ck, (void*)Cv, 3, M);
}

__global__ __launch_bounds__(256) void gemm_mma_o(
    const float* __restrict__ A,
    const __nv_bfloat16* __restrict__ Bh_all, const __nv_bfloat16* __restrict__ Bl_all,
    const float* __restrict__ bias0, float* __restrict__ C0, int M) {
    gemm_mma_body(0, A, Bh_all, Bl_all, bias0, nullptr, nullptr,
                  (void*)C0, nullptr, nullptr, 1, M);
}

// ---------------- per-node edge attention (one warp per node, unroll x2, fp16 K/V) ----------------
__device__ __forceinline__ float4 ld_half4(const __half* p) {
    uint2 r = *(const uint2*)p;
    float2 f01 = __half22float2(*(__half2*)&r.x);
    float2 f23 = __half22float2(*(__half2*)&r.y);
    return make_float4(f01.x, f01.y, f23.x, f23.y);
}

__global__ __launch_bounds__(256) void attn_kernel(const float* __restrict__ att_bias,
                                                   float* __restrict__ logits_out) {
    int warp = (blockIdx.x * blockDim.x + threadIdx.x) >> 5;
    if (warp >= NNODES) return;
    const int lane = threadIdx.x & 31;
    const int n = warp;
    const int beg = g_rowoff[n];
    const int end = g_rowoff[n + 1];

    float4 q = *(const float4*)(g_Q + (size_t)n * DIM + lane * 4);
    const int head = lane >> 2;
    const float scale = 0.25f;

    float m = -__int_as_float(0x7f800000);
    float s = 0.f;
    float4 acc = make_float4(0.f, 0.f, 0.f, 0.f);

    int j = beg;
    for (; j + 1 < end; j += 2) {
        int2 ea = g_edge2[j];
        int2 eb = g_edge2[j + 1];
        float4 ka = ld_half4(g_Kh + (size_t)ea.y * DIM + lane * 4);
        float4 va = ld_half4(g_Vh + (size_t)ea.y * DIM + lane * 4);
        float4 kb = ld_half4(g_Kh + (size_t)eb.y * DIM + lane * 4);
        float4 vb = ld_half4(g_Vh + (size_t)eb.y * DIM + lane * 4);
        float aba = __ldcs(att_bias + (size_t)ea.x * HEADS + head);
        float abb = __ldcs(att_bias + (size_t)eb.x * HEADS + head);

        float da = q.x * ka.x + q.y * ka.y + q.z * ka.z + q.w * ka.w;
        float db = q.x * kb.x + q.y * kb.y + q.z * kb.z + q.w * kb.w;
        da += __shfl_xor_sync(0xffffffffu, da, 1);
        db += __shfl_xor_sync(0xffffffffu, db, 1);
        da += __shfl_xor_sync(0xffffffffu, da, 2);
        db += __shfl_xor_sync(0xffffffffu, db, 2);
        float la = da * scale + aba;
        float lb = db * scale + abb;
        if ((lane & 3) == 0) {
            __stcs(logits_out + (size_t)ea.x * HEADS + head, la);
            __stcs(logits_out + (size_t)eb.x * HEADS + head, lb);
        }

        float nm = fmaxf(m, la);
        float f = __expf(m - nm);
        float ex = __expf(la - nm);
        s = s * f + ex;
        acc.x = acc.x * f + ex * va.x;
        acc.y = acc.y * f + ex * va.y;
        acc.z = acc.z * f + ex * va.z;
        acc.w = acc.w * f + ex * va.w;
        m = nm;

        nm = fmaxf(m, lb);
        f = __expf(m - nm);
        ex = __expf(lb - nm);
        s = s * f + ex;
        acc.x = acc.x * f + ex * vb.x;
        acc.y = acc.y * f + ex * vb.y;
        acc.z = acc.z * f + ex * vb.z;
        acc.w = acc.w * f + ex * vb.w;
        m = nm;
    }
    if (j < end) {
        int2 ea = g_edge2[j];
        float4 ka = ld_half4(g_Kh + (size_t)ea.y * DIM + lane * 4);
        float4 va = ld_half4(g_Vh + (size_t)ea.y * DIM + lane * 4);
        float aba = __ldcs(att_bias + (size_t)ea.x * HEADS + head);

        float da = q.x * ka.x + q.y * ka.y + q.z * ka.z + q.w * ka.w;
        da += __shfl_xor_sync(0xffffffffu, da, 1);
        da += __shfl_xor_sync(0xffffffffu, da, 2);
        float la = da * scale + aba;
        if ((lane & 3) == 0)
            __stcs(logits_out + (size_t)ea.x * HEADS + head, la);

        float nm = fmaxf(m, la);
        float f = __expf(m - nm);
        float ex = __expf(la - nm);
        s = s * f + ex;
        acc.x = acc.x * f + ex * va.x;
        acc.y = acc.y * f + ex * va.y;
        acc.z = acc.z * f + ex * va.z;
        acc.w = acc.w * f + ex * va.w;
        m = nm;
    }
    float inv = (s > 0.f) ? (1.f / s) : 0.f;
    float4 o = make_float4(acc.x * inv, acc.y * inv, acc.z * inv, acc.w * inv);
    __stcs((float4*)(g_agg + (size_t)n * DIM + lane * 4), o);
}

// ---------------- launch ----------------
extern "C" void kernel_launch(void* const* d_in, const int* in_sizes, int n_in,
                              void* d_out, int out_size) {
    const float* x        = (const float*)d_in[0];
    const void*  ei       = d_in[1];
    const float* att_bias = (const float*)d_in[2];
    const float* Wq = (const float*)d_in[3];
    const float* bq = (const float*)d_in[4];
    const float* Wk = (const float*)d_in[5];
    const float* bk = (const float*)d_in[6];
    const float* Wv = (const float*)d_in[7];
    const float* bv = (const float*)d_in[8];
    const float* Wo = (const float*)d_in[9];
    const float* bo = (const float*)d_in[10];

    float* out = (float*)d_out;
    float* logits = out + (size_t)NNODES * DIM;

    float*  dQ;   cudaGetSymbolAddress((void**)&dQ, g_Q);
    __half* dK;   cudaGetSymbolAddress((void**)&dK, g_Kh);
    __half* dV;   cudaGetSymbolAddress((void**)&dV, g_Vh);
    float*  dAgg; cudaGetSymbolAddress((void**)&dAgg, g_agg);
    __nv_bfloat16* dWth; cudaGetSymbolAddress((void**)&dWth, g_Wth);
    __nv_bfloat16* dWtl; cudaGetSymbolAddress((void**)&dWtl, g_Wtl);

    cudaFuncSetAttribute(gemm_mma_qkv, cudaFuncAttributeMaxDynamicSharedMemorySize, GSMEM);
    cudaFuncSetAttribute(gemm_mma_o,   cudaFuncAttributeMaxDynamicSharedMemorySize, GSMEM);

    const int EB = (EDGES + 255) / 256;
    const int NB = (NNODES + 255) / 256;
    const int MB = (NNODES + 63) / 64;        // 782
    const int AB = (NNODES * 32 + 255) / 256;

    zero_detect_kernel<<<NB, 256>>>(ei);
    conv_w_kernel<<<(4 * DIM * DIM + 255) / 256, 256>>>(Wq, Wk, Wv, Wo);
    convert_hist_kernel<<<EB, 256>>>(ei);
    blocksum_kernel<<<NBLK, SCAN_B>>>();
    gemm_mma_qkv<<<MB, 256, GSMEM>>>(x, dWth, dWtl, bq, bk, bv, dQ, dK, dV, NNODES);
    writeoff_kernel<<<NBLK, SCAN_B>>>();
    scatter_kernel<<<EB, 256>>>();

    attn_kernel<<<AB, 256>>>(att_bias, logits);

    gemm_mma_o<<<MB, 256, GSMEM>>>(dAgg, dWth + 3 * DIM * DIM, dWtl + 3 * DIM * DIM,
                                   bo, out, NNODES);
}

// round 17
// speedup vs baseline: 1.0435x; 1.0435x over previous
#include <cuda_runtime.h>
#include <cuda_bf16.h>
#include <cstdint>

#define NNODES 50000
#define EDGES  800000
#define DIM    128
#define HEADS  8
#define SCAN_B 256
#define NBLK   ((NNODES + SCAN_B - 1) / SCAN_B)   // 196

// ---------------- scratch (static device arrays; no allocs allowed) ----------------
__device__ int   g_is64;
__device__ int2  g_ds[EDGES];           // (dst, src) int32
__device__ int   g_deg[NNODES];
__device__ int   g_rowoff[NNODES + 1];
__device__ int   g_cursor[NNODES];
__device__ int2  g_edge2[EDGES];        // (orig edge id, src node) in CSR order
__device__ int   g_blocksum[NBLK];
__device__ float g_Q[(size_t)NNODES * DIM];
__device__ float g_K[(size_t)NNODES * DIM];
__device__ float g_V[(size_t)NNODES * DIM];
__device__ float g_agg[(size_t)NNODES * DIM];
__device__ __nv_bfloat16 g_Wth[4 * DIM * DIM];  // transposed [N][K] hi
__device__ __nv_bfloat16 g_Wtl[4 * DIM * DIM];  // transposed [N][K] lo

// ---------------- helpers ----------------
__device__ __forceinline__ uint32_t smem_u32(const void* p) {
    uint32_t a;
    asm("{ .reg .u64 t; cvta.to.shared.u64 t, %1; cvt.u32.u64 %0, t; }" : "=r"(a) : "l"(p));
    return a;
}
__device__ __forceinline__ void ldsm_x4(uint32_t* r, uint32_t addr) {
    asm volatile("ldmatrix.sync.aligned.m8n8.x4.shared.b16 {%0,%1,%2,%3}, [%4];"
                 : "=r"(r[0]), "=r"(r[1]), "=r"(r[2]), "=r"(r[3]) : "r"(addr));
}
__device__ __forceinline__ void mma16816(float* d, const uint32_t* a, const uint32_t* b) {
    asm volatile(
        "mma.sync.aligned.m16n8k16.row.col.f32.bf16.bf16.f32 "
        "{%0,%1,%2,%3}, {%4,%5,%6,%7}, {%8,%9}, {%0,%1,%2,%3};"
        : "+f"(d[0]), "+f"(d[1]), "+f"(d[2]), "+f"(d[3])
        : "r"(a[0]), "r"(a[1]), "r"(a[2]), "r"(a[3]), "r"(b[0]), "r"(b[1]));
}

// ---------------- fused: zero deg + dtype detect + weight transpose/split ----------------
// grid: 256 blocks x 256 threads. i < NNODES -> zero deg; i < 65536 -> conv_w.
__global__ void prep_kernel(const void* ei,
                            const float* __restrict__ W0, const float* __restrict__ W1,
                            const float* __restrict__ W2, const float* __restrict__ W3) {
    int i = blockIdx.x * blockDim.x + threadIdx.x;
    if (i < NNODES) g_deg[i] = 0;
    if (i == 0) {
        const int* w = (const int*)ei;
        int is64 = 1;
        for (int t = 0; t < 64; t++) {
            int lo = w[2 * t], hi = w[2 * t + 1];
            if (hi != 0 || lo < 0 || lo >= NNODES) { is64 = 0; break; }
        }
        g_is64 = is64;
    }
    if (i < 4 * DIM * DIM) {
        int mat = i >> 14;
        int idx = i & 16383;
        int n = idx >> 7;
        int k = idx & 127;
        const float* W = (mat == 0) ? W0 : (mat == 1) ? W1 : (mat == 2) ? W2 : W3;
        float v = W[k * DIM + n];
        __nv_bfloat16 h = __float2bfloat16_rn(v);
        __nv_bfloat16 l = __float2bfloat16_rn(v - __bfloat162float(h));
        g_Wth[mat * DIM * DIM + idx] = h;
        g_Wtl[mat * DIM * DIM + idx] = l;
    }
}

__global__ void convert_hist_kernel(const void* ei) {
    int i = blockIdx.x * blockDim.x + threadIdx.x;
    if (i >= EDGES) return;
    int d, s;
    if (g_is64) {
        const long long* p = (const long long*)ei;
        d = (int)p[i];
        s = (int)p[EDGES + i];
    } else {
        const int* p = (const int*)ei;
        d = p[i];
        s = p[EDGES + i];
    }
    g_ds[i] = make_int2(d, s);
    atomicAdd(&g_deg[d], 1);
}

__global__ void blocksum_kernel() {
    __shared__ int red[SCAN_B];
    int i = blockIdx.x * SCAN_B + threadIdx.x;
    int v = (i < NNODES) ? g_deg[i] : 0;
    red[threadIdx.x] = v;
    __syncthreads();
    #pragma unroll
    for (int off = SCAN_B / 2; off > 0; off >>= 1) {
        if (threadIdx.x < off) red[threadIdx.x] += red[threadIdx.x + off];
        __syncthreads();
    }
    if (threadIdx.x == 0) g_blocksum[blockIdx.x] = red[0];
}

// fused: every block redundantly scans the 196 block sums, then scans its own
// 256 degrees and writes rowoff/cursor.
__global__ void writeoff_kernel() {
    __shared__ int sc[SCAN_B];
    const int tid = threadIdx.x;

    int bv = (tid < NBLK) ? g_blocksum[tid] : 0;
    sc[tid] = bv;
    __syncthreads();
    #pragma unroll
    for (int off = 1; off < SCAN_B; off <<= 1) {
        int u = (tid >= off) ? sc[tid - off] : 0;
        __syncthreads();
        sc[tid] += u;
        __syncthreads();
    }
    int blockoff = sc[blockIdx.x] - g_blocksum[blockIdx.x];
    int total = sc[NBLK - 1];
    __syncthreads();

    int i = blockIdx.x * SCAN_B + tid;
    int v = (i < NNODES) ? g_deg[i] : 0;
    sc[tid] = v;
    __syncthreads();
    #pragma unroll
    for (int off = 1; off < SCAN_B; off <<= 1) {
        int u = (tid >= off) ? sc[tid - off] : 0;
        __syncthreads();
        sc[tid] += u;
        __syncthreads();
    }
    if (i < NNODES) {
        int off = blockoff + sc[tid] - v;
        g_rowoff[i] = off;
        g_cursor[i] = off;
    }
    if (blockIdx.x == 0 && tid == 0) g_rowoff[NNODES] = total;
}

// ---------------- hybrid: QKV split-bf16 GEMM (blocks < MB) + CSR scatter (rest) ----------------
#define LDA 136
#define A_TILE (64 * LDA * 2)             // 17408
#define B_TILE (128 * LDA * 2)            // 34816
#define OFF_AH 0
#define OFF_AL A_TILE
#define OFF_BH (2 * A_TILE)
#define OFF_BL (2 * A_TILE + B_TILE)
#define GSMEM  (2 * A_TILE + 2 * B_TILE)  // 104448 -> 2 CTAs/SM
#define MB_GEMM ((NNODES + 63) / 64)      // 782
#define EB_SCAT ((EDGES + 255) / 256)     // 3125

__device__ __forceinline__ void gemm_body(
    const float* __restrict__ A,
    const __nv_bfloat16* __restrict__ Bh_all, const __nv_bfloat16* __restrict__ Bl_all,
    const float* __restrict__ bias0, const float* __restrict__ bias1,
    const float* __restrict__ bias2,
    float* __restrict__ C0, float* __restrict__ C1, float* __restrict__ C2,
    int count, int M, int block) {
    extern __shared__ char sm[];
    const uint32_t sb = smem_u32(sm);
    const int tid = threadIdx.x, wid = tid >> 5, lane = tid & 31;
    const int bm = block * 64;

    // stage A (64 rows): load fp32, split to (hi, lo) bf16 in registers
    #pragma unroll
    for (int it = 0; it < 8; ++it) {
        int g = tid + it * 256;            // 0..2047, 4-col groups
        int row = g >> 5;
        int col = (g & 31) << 2;
        int gr = bm + row;
        float4 v = make_float4(0.f, 0.f, 0.f, 0.f);
        if (gr < M) v = *(const float4*)(A + (size_t)gr * DIM + col);
        float a[4] = {v.x, v.y, v.z, v.w};
        __nv_bfloat16 h[4], l[4];
        #pragma unroll
        for (int u = 0; u < 4; u++) {
            h[u] = __float2bfloat16_rn(a[u]);
            l[u] = __float2bfloat16_rn(a[u] - __bfloat162float(h[u]));
        }
        *(unsigned long long*)(sm + OFF_AH + (row * LDA + col) * 2) = *(unsigned long long*)h;
        *(unsigned long long*)(sm + OFF_AL + (row * LDA + col) * 2) = *(unsigned long long*)l;
    }

    // warp tiling: 2 warps in M (32 rows each), 4 warps in N (32 cols each)
    const int wm = wid & 1, wn = wid >> 1;
    const int m0 = wm * 32, n0 = wn * 32;
    const int g = lane >> 2, t = lane & 3;

    const int ar = lane & 15, ac = (lane >> 4) << 3;
    const int nn = (lane & 7) + ((lane >> 4) << 3);
    const int kkb = ((lane >> 3) & 1) << 3;

    #pragma unroll 1
    for (int w = 0; w < count; w++) {
        const __nv_bfloat16* Bh = Bh_all + (size_t)w * DIM * DIM;
        const __nv_bfloat16* Bl = Bl_all + (size_t)w * DIM * DIM;
        const float* bias = (w == 0) ? bias0 : (w == 1) ? bias1 : bias2;
        float* C = (w == 0) ? C0 : (w == 1) ? C1 : C2;

        __syncthreads();
        #pragma unroll
        for (int it = 0; it < 16; ++it) {
            int gg = tid + it * 256;       // 0..4095 (128 rows x 32 groups)
            int row = gg >> 5;
            int col = (gg & 31) << 2;
            *(unsigned long long*)(sm + OFF_BH + (row * LDA + col) * 2) =
                *(const unsigned long long*)(Bh + row * DIM + col);
            *(unsigned long long*)(sm + OFF_BL + (row * LDA + col) * 2) =
                *(const unsigned long long*)(Bl + row * DIM + col);
        }
        __syncthreads();

        float acc[2][4][4];
        #pragma unroll
        for (int mt = 0; mt < 2; mt++)
            #pragma unroll
            for (int nt = 0; nt < 4; nt++)
                #pragma unroll
                for (int u = 0; u < 4; u++) acc[mt][nt][u] = 0.f;

        #pragma unroll
        for (int k = 0; k < 8; k++) {
            const int k0 = k * 16;
            uint32_t aH[2][4], aL[2][4], bH[2][4], bL[2][4];
            #pragma unroll
            for (int mt = 0; mt < 2; mt++) {
                uint32_t off = ((m0 + mt * 16 + ar) * LDA + k0 + ac) * 2;
                ldsm_x4(aH[mt], sb + OFF_AH + off);
                ldsm_x4(aL[mt], sb + OFF_AL + off);
            }
            #pragma unroll
            for (int nb = 0; nb < 2; nb++) {
                uint32_t off = ((n0 + nb * 16 + nn) * LDA + k0 + kkb) * 2;
                ldsm_x4(bH[nb], sb + OFF_BH + off);
                ldsm_x4(bL[nb], sb + OFF_BL + off);
            }
            #pragma unroll
            for (int mt = 0; mt < 2; mt++)
                #pragma unroll
                for (int nb = 0; nb < 2; nb++) {
                    mma16816(acc[mt][2 * nb],     aH[mt], bH[nb]);
                    mma16816(acc[mt][2 * nb],     aH[mt], bL[nb]);
                    mma16816(acc[mt][2 * nb],     aL[mt], bH[nb]);
                    mma16816(acc[mt][2 * nb + 1], aH[mt], bH[nb] + 2);
                    mma16816(acc[mt][2 * nb + 1], aH[mt], bL[nb] + 2);
                    mma16816(acc[mt][2 * nb + 1], aL[mt], bH[nb] + 2);
                }
        }

        #pragma unroll
        for (int mt = 0; mt < 2; mt++) {
            int r0 = bm + m0 + mt * 16 + g;
            #pragma unroll
            for (int nt = 0; nt < 4; nt++) {
                int col = n0 + nt * 8 + 2 * t;
                float bx = __ldg(bias + col), by = __ldg(bias + col + 1);
                if (r0 < M) {
                    float2 o = make_float2(acc[mt][nt][0] + bx, acc[mt][nt][1] + by);
                    *(float2*)(C + (size_t)r0 * DIM + col) = o;
                }
                if (r0 + 8 < M) {
                    float2 o = make_float2(acc[mt][nt][2] + bx, acc[mt][nt][3] + by);
                    *(float2*)(C + (size_t)(r0 + 8) * DIM + col) = o;
                }
            }
        }
    }
}

// hybrid kernel: first MB_GEMM blocks run the QKV GEMM, remaining blocks scatter edges.
__global__ __launch_bounds__(256) void gemm_qkv_scatter(
    const float* __restrict__ A,
    const __nv_bfloat16* __restrict__ Bh_all, const __nv_bfloat16* __restrict__ Bl_all,
    const float* __restrict__ bias0, const float* __restrict__ bias1,
    const float* __restrict__ bias2,
    float* __restrict__ Cq, float* __restrict__ Ck, float* __restrict__ Cv, int M) {
    if (blockIdx.x < MB_GEMM) {
        gemm_body(A, Bh_all, Bl_all, bias0, bias1, bias2, Cq, Ck, Cv, 3, M, blockIdx.x);
    } else {
        int i = (blockIdx.x - MB_GEMM) * blockDim.x + threadIdx.x;
        if (i < EDGES) {
            int2 ds = g_ds[i];
            int p = atomicAdd(&g_cursor[ds.x], 1);
            g_edge2[p] = make_int2(i, ds.y);
        }
    }
}

__global__ __launch_bounds__(256) void gemm_mma_o(
    const float* __restrict__ A,
    const __nv_bfloat16* __restrict__ Bh_all, const __nv_bfloat16* __restrict__ Bl_all,
    const float* __restrict__ bias0, float* __restrict__ C0, int M) {
    gemm_body(A, Bh_all, Bl_all, bias0, nullptr, nullptr, C0, nullptr, nullptr, 1, M,
              blockIdx.x);
}

// ---------------- per-node edge attention (one warp per node, unroll x2) ----------------
__global__ __launch_bounds__(256) void attn_kernel(const float* __restrict__ att_bias,
                                                   float* __restrict__ logits_out) {
    int warp = (blockIdx.x * blockDim.x + threadIdx.x) >> 5;
    if (warp >= NNODES) return;
    const int lane = threadIdx.x & 31;
    const int n = warp;
    const int beg = g_rowoff[n];
    const int end = g_rowoff[n + 1];

    float4 q = *(const float4*)(g_Q + (size_t)n * DIM + lane * 4);
    const int head = lane >> 2;
    const float scale = 0.25f;

    float m = -__int_as_float(0x7f800000);
    float s = 0.f;
    float4 acc = make_float4(0.f, 0.f, 0.f, 0.f);

    int j = beg;
    for (; j + 1 < end; j += 2) {
        int2 ea = g_edge2[j];
        int2 eb = g_edge2[j + 1];
        float4 ka = *(const float4*)(g_K + (size_t)ea.y * DIM + lane * 4);
        float4 va = *(const float4*)(g_V + (size_t)ea.y * DIM + lane * 4);
        float4 kb = *(const float4*)(g_K + (size_t)eb.y * DIM + lane * 4);
        float4 vb = *(const float4*)(g_V + (size_t)eb.y * DIM + lane * 4);
        float aba = __ldcs(att_bias + (size_t)ea.x * HEADS + head);
        float abb = __ldcs(att_bias + (size_t)eb.x * HEADS + head);

        float da = q.x * ka.x + q.y * ka.y + q.z * ka.z + q.w * ka.w;
        float db = q.x * kb.x + q.y * kb.y + q.z * kb.z + q.w * kb.w;
        da += __shfl_xor_sync(0xffffffffu, da, 1);
        db += __shfl_xor_sync(0xffffffffu, db, 1);
        da += __shfl_xor_sync(0xffffffffu, da, 2);
        db += __shfl_xor_sync(0xffffffffu, db, 2);
        float la = da * scale + aba;
        float lb = db * scale + abb;
        if ((lane & 3) == 0) {
            __stcs(logits_out + (size_t)ea.x * HEADS + head, la);
            __stcs(logits_out + (size_t)eb.x * HEADS + head, lb);
        }

        float nm = fmaxf(m, la);
        float f = __expf(m - nm);
        float ex = __expf(la - nm);
        s = s * f + ex;
        acc.x = acc.x * f + ex * va.x;
        acc.y = acc.y * f + ex * va.y;
        acc.z = acc.z * f + ex * va.z;
        acc.w = acc.w * f + ex * va.w;
        m = nm;

        nm = fmaxf(m, lb);
        f = __expf(m - nm);
        ex = __expf(lb - nm);
        s = s * f + ex;
        acc.x = acc.x * f + ex * vb.x;
        acc.y = acc.y * f + ex * vb.y;
        acc.z = acc.z * f + ex * vb.z;
        acc.w = acc.w * f + ex * vb.w;
        m = nm;
    }
    if (j < end) {
        int2 ea = g_edge2[j];
        float4 ka = *(const float4*)(g_K + (size_t)ea.y * DIM + lane * 4);
        float4 va = *(const float4*)(g_V + (size_t)ea.y * DIM + lane * 4);
        float aba = __ldcs(att_bias + (size_t)ea.x * HEADS + head);

        float da = q.x * ka.x + q.y * ka.y + q.z * ka.z + q.w * ka.w;
        da += __shfl_xor_sync(0xffffffffu, da, 1);
        da += __shfl_xor_sync(0xffffffffu, da, 2);
        float la = da * scale + aba;
        if ((lane & 3) == 0)
            __stcs(logits_out + (size_t)ea.x * HEADS + head, la);

        float nm = fmaxf(m, la);
        float f = __expf(m - nm);
        float ex = __expf(la - nm);
        s = s * f + ex;
        acc.x = acc.x * f + ex * va.x;
        acc.y = acc.y * f + ex * va.y;
        acc.z = acc.z * f + ex * va.z;
        acc.w = acc.w * f + ex * va.w;
        m = nm;
    }
    float inv = (s > 0.f) ? (1.f / s) : 0.f;
    float4 o = make_float4(acc.x * inv, acc.y * inv, acc.z * inv, acc.w * inv);
    __stcs((float4*)(g_agg + (size_t)n * DIM + lane * 4), o);
}

// ---------------- launch ----------------
extern "C" void kernel_launch(void* const* d_in, const int* in_sizes, int n_in,
                              void* d_out, int out_size) {
    const float* x        = (const float*)d_in[0];
    const void*  ei       = d_in[1];
    const float* att_bias = (const float*)d_in[2];
    const float* Wq = (const float*)d_in[3];
    const float* bq = (const float*)d_in[4];
    const float* Wk = (const float*)d_in[5];
    const float* bk = (const float*)d_in[6];
    const float* Wv = (const float*)d_in[7];
    const float* bv = (const float*)d_in[8];
    const float* Wo = (const float*)d_in[9];
    const float* bo = (const float*)d_in[10];

    float* out = (float*)d_out;
    float* logits = out + (size_t)NNODES * DIM;

    float* dQ;   cudaGetSymbolAddress((void**)&dQ, g_Q);
    float* dK;   cudaGetSymbolAddress((void**)&dK, g_K);
    float* dV;   cudaGetSymbolAddress((void**)&dV, g_V);
    float* dAgg; cudaGetSymbolAddress((void**)&dAgg, g_agg);
    __nv_bfloat16* dWth; cudaGetSymbolAddress((void**)&dWth, g_Wth);
    __nv_bfloat16* dWtl; cudaGetSymbolAddress((void**)&dWtl, g_Wtl);

    cudaFuncSetAttribute(gemm_qkv_scatter, cudaFuncAttributeMaxDynamicSharedMemorySize, GSMEM);
    cudaFuncSetAttribute(gemm_mma_o,       cudaFuncAttributeMaxDynamicSharedMemorySize, GSMEM);

    const int EB = (EDGES + 255) / 256;       // 3125
    const int AB = (NNODES * 32 + 255) / 256;

    // launch #1..#5, so attn_kernel is launch #6 (ncu -s 5 -c 1 captures it)
    prep_kernel<<<256, 256>>>(ei, Wq, Wk, Wv, Wo);
    convert_hist_kernel<<<EB, 256>>>(ei);
    blocksum_kernel<<<NBLK, SCAN_B>>>();
    writeoff_kernel<<<NBLK, SCAN_B>>>();
    gemm_qkv_scatter<<<MB_GEMM + EB_SCAT, 256, GSMEM>>>(x, dWth, dWtl, bq, bk, bv,
                                                        dQ, dK, dV, NNODES);

    attn_kernel<<<AB, 256>>>(att_bias, logits);

    gemm_mma_o<<<MB_GEMM, 256, GSMEM>>>(dAgg, dWth + 3 * DIM * DIM, dWtl + 3 * DIM * DIM,
                                        bo, out, NNODES);
}